// round 1
// baseline (speedup 1.0000x reference)
#include <cuda_runtime.h>

#define O_NODES 512
#define DD 128              // Din = Dout = H = 128
#define ALPHA 0.2f
#define EPB 8

// ---------------- scratch (static device globals; no allocations) ----------
__device__ float g_Wh[O_NODES * DD];
__device__ float g_f1[O_NODES];
__device__ float g_f2[O_NODES];
__device__ float g_Ab[O_NODES * DD];     // h'[i] @ W1[0:128]   + b1
__device__ float g_C [O_NODES * DD];     // h'[i] @ W1[256:384]
__device__ float g_pooled[O_NODES * DD];
__device__ int   g_cnt[O_NODES];

// ---------------- K_init: zero pooled + counts (graph replays need this) ---
__global__ void k_init() {
    int idx = blockIdx.x * blockDim.x + threadIdx.x;
    if (idx < O_NODES * DD) g_pooled[idx] = 0.0f;
    if (idx < O_NODES) g_cnt[idx] = 0;
}

// ---------------- K0: Wh = obj @ W ; f1 = Wh@a1 ; f2 = Wh@a2 ---------------
__global__ void k0_wh(const float* __restrict__ obj,
                      const float* __restrict__ W,
                      const float* __restrict__ a) {
    int i = blockIdx.x;
    int d = threadIdx.x;             // 0..127
    __shared__ float xs[DD];
    __shared__ float r1[4], r2[4];
    xs[d] = obj[i * DD + d];
    __syncthreads();
    float acc = 0.0f;
#pragma unroll 8
    for (int k = 0; k < DD; k++) acc = fmaf(xs[k], W[k * DD + d], acc);
    g_Wh[i * DD + d] = acc;

    float p1 = acc * a[d];
    float p2 = acc * a[DD + d];
#pragma unroll
    for (int off = 16; off > 0; off >>= 1) {
        p1 += __shfl_down_sync(0xffffffffu, p1, off);
        p2 += __shfl_down_sync(0xffffffffu, p2, off);
    }
    if ((d & 31) == 0) { r1[d >> 5] = p1; r2[d >> 5] = p2; }
    __syncthreads();
    if (d == 0) {
        g_f1[i] = r1[0] + r1[1] + r1[2] + r1[3];
        g_f2[i] = r2[0] + r2[1] + r2[2] + r2[3];
    }
}

// ---------------- K2: attention softmax -> h' -> A,C precompute ------------
__global__ void k2_attn(const float* __restrict__ W1,
                        const float* __restrict__ b1) {
    int i = blockIdx.x;
    int d = threadIdx.x;             // 0..127
    __shared__ float att[O_NODES];
    __shared__ float red[4];
    __shared__ float hps[DD];

    float fi = g_f1[i];
    float ev[4];
    float m = -1e30f;
#pragma unroll
    for (int u = 0; u < 4; u++) {
        int j = d + u * 128;
        float x = fi + g_f2[j];
        x = (x > 0.0f) ? x : ALPHA * x;     // leaky_relu
        if (j == i) x = -1e30f;             // diagonal masked
        ev[u] = x;
        m = fmaxf(m, x);
    }
#pragma unroll
    for (int off = 16; off > 0; off >>= 1)
        m = fmaxf(m, __shfl_xor_sync(0xffffffffu, m, off));
    if ((d & 31) == 0) red[d >> 5] = m;
    __syncthreads();
    m = fmaxf(fmaxf(red[0], red[1]), fmaxf(red[2], red[3]));
    __syncthreads();

    float s = 0.0f;
#pragma unroll
    for (int u = 0; u < 4; u++) {
        int j = d + u * 128;
        float p = (j == i) ? 0.0f : expf(ev[u] - m);
        att[j] = p;
        s += p;
    }
#pragma unroll
    for (int off = 16; off > 0; off >>= 1)
        s += __shfl_xor_sync(0xffffffffu, s, off);
    if ((d & 31) == 0) red[d >> 5] = s;
    __syncthreads();
    float denom = red[0] + red[1] + red[2] + red[3];
    __syncthreads();

    // h'[i][d] = relu( (sum_j att_j * Wh[j][d]) / denom )
    float acc = 0.0f;
#pragma unroll 8
    for (int j = 0; j < O_NODES; j++)
        acc = fmaf(att[j], g_Wh[j * DD + d], acc);
    float hp = acc / denom;
    hp = fmaxf(hp, 0.0f);
    hps[d] = hp;
    __syncthreads();

    // A[i][d] = sum_k hp[k]*W1[k][d] (+b1) ;  C[i][d] = sum_k hp[k]*W1[256+k][d]
    float A = 0.0f, C = 0.0f;
#pragma unroll 8
    for (int k = 0; k < DD; k++) {
        float h = hps[k];
        A = fmaf(h, W1[k * DD + d], A);
        C = fmaf(h, W1[(256 + k) * DD + d], C);
    }
    g_Ab[i * DD + d] = A + b1[d];
    g_C [i * DD + d] = C;
}

// ---------------- K_count ---------------------------------------------------
__global__ void k_count(const int* __restrict__ edges, int T) {
    int t = blockIdx.x * blockDim.x + threadIdx.x;
    if (t < T) {
        atomicAdd(&g_cnt[edges[2 * t]], 1);
        atomicAdd(&g_cnt[edges[2 * t + 1]], 1);
    }
}

// ---------------- K3: edge MLP (dominant kernel) ---------------------------
// grid = 1024: block b handles s = b/2, edges e in [half*256, half*256 + (half?255:256))
__global__ void __launch_bounds__(128) k3_edge(
        const float* __restrict__ pred,
        const int*   __restrict__ edges,
        const float* __restrict__ W1,
        const float* __restrict__ W2,
        const float* __restrict__ b2,
        float* __restrict__ out_np) {
    int s    = blockIdx.x >> 1;
    int half = blockIdx.x & 1;
    int d    = threadIdx.x;          // 0..127
    int e_start = half * 256;
    int e_count = half ? 255 : 256;
    int base = s * (O_NODES - 1);    // first edge index for this s row

    __shared__ float p_s[EPB][DD];
    __shared__ float h1_s[EPB][DD];
    __shared__ int   o_s[EPB];
    __shared__ float Ab_s[DD];

    Ab_s[d] = g_Ab[s * DD + d];
    const float* W1b = W1 + 128 * DD;
    float b2a = b2[d], b2b = b2[128 + d], b2c = b2[256 + d];
    float sAcc = 0.0f;

    int ngroups = (e_count + EPB - 1) / EPB;
    for (int g = 0; g < ngroups; g++) {
        int e0 = e_start + g * EPB;
        int nval = e_count - g * EPB; if (nval > EPB) nval = EPB;
        __syncthreads();   // prev iter done reading o_s / h1_s
        // load edge tile
#pragma unroll
        for (int e = 0; e < EPB; e++) {
            p_s[e][d] = (e < nval) ? pred[(size_t)(base + e0 + e) * DD + d] : 0.0f;
        }
        if (d < EPB) o_s[d] = (d < nval) ? edges[2 * (base + e0 + d) + 1] : 0;
        __syncthreads();

        // ---- phase 1: h1 = relu(Ab[s] + C[o] + p @ W1b) ----
        float acc[EPB];
#pragma unroll
        for (int e = 0; e < EPB; e++)
            acc[e] = Ab_s[d] + ((e < nval) ? g_C[o_s[e] * DD + d] : 0.0f);

#pragma unroll 4
        for (int k = 0; k < DD; k += 4) {
            float w0 = W1b[(k + 0) * DD + d];
            float w1 = W1b[(k + 1) * DD + d];
            float w2 = W1b[(k + 2) * DD + d];
            float w3 = W1b[(k + 3) * DD + d];
#pragma unroll
            for (int e = 0; e < EPB; e++) {
                float4 p = *(const float4*)&p_s[e][k];
                acc[e] = fmaf(p.x, w0, acc[e]);
                acc[e] = fmaf(p.y, w1, acc[e]);
                acc[e] = fmaf(p.z, w2, acc[e]);
                acc[e] = fmaf(p.w, w3, acc[e]);
            }
        }
#pragma unroll
        for (int e = 0; e < EPB; e++)
            h1_s[e][d] = fmaxf(acc[e], 0.0f);
        __syncthreads();

        // ---- phase 2: new_t = relu(h1 @ W2 + b2), 3 cols per thread ----
        float a0[EPB], a1[EPB], a2[EPB];
#pragma unroll
        for (int e = 0; e < EPB; e++) { a0[e] = b2a; a1[e] = b2b; a2[e] = b2c; }

#pragma unroll 2
        for (int k = 0; k < DD; k += 4) {
            float wa0 = W2[(k + 0) * 384 + d];
            float wa1 = W2[(k + 1) * 384 + d];
            float wa2 = W2[(k + 2) * 384 + d];
            float wa3 = W2[(k + 3) * 384 + d];
            float wb0 = W2[(k + 0) * 384 + 128 + d];
            float wb1 = W2[(k + 1) * 384 + 128 + d];
            float wb2 = W2[(k + 2) * 384 + 128 + d];
            float wb3 = W2[(k + 3) * 384 + 128 + d];
            float wc0 = W2[(k + 0) * 384 + 256 + d];
            float wc1 = W2[(k + 1) * 384 + 256 + d];
            float wc2 = W2[(k + 2) * 384 + 256 + d];
            float wc3 = W2[(k + 3) * 384 + 256 + d];
#pragma unroll
            for (int e = 0; e < EPB; e++) {
                float4 h = *(const float4*)&h1_s[e][k];
                a0[e] = fmaf(h.x, wa0, a0[e]); a0[e] = fmaf(h.y, wa1, a0[e]);
                a0[e] = fmaf(h.z, wa2, a0[e]); a0[e] = fmaf(h.w, wa3, a0[e]);
                a1[e] = fmaf(h.x, wb0, a1[e]); a1[e] = fmaf(h.y, wb1, a1[e]);
                a1[e] = fmaf(h.z, wb2, a1[e]); a1[e] = fmaf(h.w, wb3, a1[e]);
                a2[e] = fmaf(h.x, wc0, a2[e]); a2[e] = fmaf(h.y, wc1, a2[e]);
                a2[e] = fmaf(h.z, wc2, a2[e]); a2[e] = fmaf(h.w, wc3, a2[e]);
            }
        }

        // ---- outputs ----
#pragma unroll
        for (int e = 0; e < EPB; e++) {
            if (e < nval) {
                int t = base + e0 + e;
                sAcc += fmaxf(a0[e], 0.0f);                       // new_s running sum
                out_np[(size_t)t * DD + d] = fmaxf(a1[e], 0.0f);  // new_p
                atomicAdd(&g_pooled[o_s[e] * DD + d], fmaxf(a2[e], 0.0f)); // new_o
            }
        }
    }
    atomicAdd(&g_pooled[s * DD + d], sAcc);
}

// ---------------- K4: pooled/counts -> MLP2 -> new_obj ---------------------
__global__ void k4_out(const float* __restrict__ W3, const float* __restrict__ b3,
                       const float* __restrict__ W4, const float* __restrict__ b4,
                       float* __restrict__ out) {
    int i = blockIdx.x;
    int j = threadIdx.x;             // 0..255
    __shared__ float pn[DD];
    __shared__ float g1[256];
    if (j < DD) {
        float c = (float)g_cnt[i];
        c = fmaxf(c, 1.0f);
        pn[j] = g_pooled[i * DD + j] / c;
    }
    __syncthreads();
    float acc = b3[j];
#pragma unroll 8
    for (int k = 0; k < DD; k++) acc = fmaf(pn[k], W3[k * 256 + j], acc);
    g1[j] = fmaxf(acc, 0.0f);
    __syncthreads();
    if (j < DD) {
        float acc2 = b4[j];
#pragma unroll 8
        for (int k = 0; k < 256; k++) acc2 = fmaf(g1[k], W4[k * DD + j], acc2);
        out[i * DD + j] = fmaxf(acc2, 0.0f);
    }
}

// ---------------- launch ----------------------------------------------------
extern "C" void kernel_launch(void* const* d_in, const int* in_sizes, int n_in,
                              void* d_out, int out_size) {
    const float* obj  = (const float*)d_in[0];
    const float* pred = (const float*)d_in[1];
    const int*   edges= (const int*)  d_in[2];
    const float* W    = (const float*)d_in[3];
    const float* a    = (const float*)d_in[4];
    const float* W1   = (const float*)d_in[5];
    const float* b1   = (const float*)d_in[6];
    const float* W2   = (const float*)d_in[7];
    const float* b2   = (const float*)d_in[8];
    const float* W3   = (const float*)d_in[9];
    const float* b3   = (const float*)d_in[10];
    const float* W4   = (const float*)d_in[11];
    const float* b4   = (const float*)d_in[12];
    float* out = (float*)d_out;
    int T = in_sizes[2] / 2;

    k_init<<<256, 256>>>();
    k0_wh<<<O_NODES, 128>>>(obj, W, a);
    k2_attn<<<O_NODES, 128>>>(W1, b1);
    k_count<<<(T + 255) / 256, 256>>>(edges, T);
    k3_edge<<<2 * O_NODES, 128>>>(pred, edges, W1, W2, b2, out + O_NODES * DD);
    k4_out<<<O_NODES, 256>>>(W3, b3, W4, b4, out);
}

// round 5
// speedup vs baseline: 1.1395x; 1.1395x over previous
#include <cuda_runtime.h>
#include <cuda_bf16.h>
#include <cstdint>

#define O_NODES 512
#define DD 128
#define ALPHA 0.2f
#define T_EDGES 261632
#define N_CTAS 1022            // T_EDGES / 256

// ------------------------- device scratch (static; no allocs) ---------------
__device__ float g_Wh[O_NODES * DD];
__device__ float g_f1[O_NODES], g_f2[O_NODES];
__device__ float g_Ab[O_NODES * DD], g_C[O_NODES * DD];
__device__ float g_pooled[O_NODES * DD];
__device__ uint32_t g_w1f[16384];            // W1b frags: [kt8][nt16][lane32][q4]
__device__ uint32_t g_w2f[49152];            // W2 frags:  [kt2 8][gnt48][lane32][q4]
__device__ __nv_bfloat16 g_so[(size_t)O_NODES * O_NODES * DD];  // [o][s][128]

// ------------------------- helpers ------------------------------------------
__device__ __forceinline__ uint32_t smem_u32(const void* p) {
    uint32_t a;
    asm("{ .reg .u64 t; cvta.to.shared.u64 t, %1; cvt.u32.u64 %0, t; }" : "=r"(a) : "l"(p));
    return a;
}
__device__ __forceinline__ uint32_t pack2(float x, float y) {
    __nv_bfloat162 h = __floats2bfloat162_rn(x, y);
    return *(uint32_t*)&h;
}
__device__ __forceinline__ void split2(float x, float y, uint32_t& hi, uint32_t& lo) {
    __nv_bfloat162 h = __floats2bfloat162_rn(x, y);
    float hx = __bfloat162float(h.x), hy = __bfloat162float(h.y);
    __nv_bfloat162 l = __floats2bfloat162_rn(x - hx, y - hy);
    hi = *(uint32_t*)&h;
    lo = *(uint32_t*)&l;
}
__device__ __forceinline__ void mma_bf16(float* d, const uint32_t* a, uint32_t b0, uint32_t b1) {
    asm volatile("mma.sync.aligned.m16n8k16.row.col.f32.bf16.bf16.f32 "
                 "{%0,%1,%2,%3}, {%4,%5,%6,%7}, {%8,%9}, {%0,%1,%2,%3};"
                 : "+f"(d[0]), "+f"(d[1]), "+f"(d[2]), "+f"(d[3])
                 : "r"(a[0]), "r"(a[1]), "r"(a[2]), "r"(a[3]), "r"(b0), "r"(b1));
}
__device__ __forceinline__ void cp_async16(uint32_t dst, const void* src) {
    asm volatile("cp.async.cg.shared.global [%0], [%1], 16;" :: "r"(dst), "l"(src) : "memory");
}

// ---------------- k_init: zero pooled (graph replays) -----------------------
__global__ void k_init() {
    int idx = blockIdx.x * blockDim.x + threadIdx.x;
    if (idx < O_NODES * DD) g_pooled[idx] = 0.0f;
}

// ---------------- K0: Wh = obj @ W ; f1,f2 ----------------------------------
__global__ void k0_wh(const float* __restrict__ obj, const float* __restrict__ W,
                      const float* __restrict__ a) {
    int i = blockIdx.x, d = threadIdx.x;
    __shared__ float xs[DD]; __shared__ float r1[4], r2[4];
    xs[d] = obj[i * DD + d];
    __syncthreads();
    float acc = 0.0f;
#pragma unroll 8
    for (int k = 0; k < DD; k++) acc = fmaf(xs[k], W[k * DD + d], acc);
    g_Wh[i * DD + d] = acc;
    float p1 = acc * a[d], p2 = acc * a[DD + d];
#pragma unroll
    for (int off = 16; off > 0; off >>= 1) {
        p1 += __shfl_down_sync(0xffffffffu, p1, off);
        p2 += __shfl_down_sync(0xffffffffu, p2, off);
    }
    if ((d & 31) == 0) { r1[d >> 5] = p1; r2[d >> 5] = p2; }
    __syncthreads();
    if (d == 0) { g_f1[i] = r1[0]+r1[1]+r1[2]+r1[3]; g_f2[i] = r2[0]+r2[1]+r2[2]+r2[3]; }
}

// ---------------- K2: softmax attention -> h' -> Ab,C -----------------------
__global__ void k2_attn(const float* __restrict__ W1, const float* __restrict__ b1) {
    int i = blockIdx.x, d = threadIdx.x;
    __shared__ float att[O_NODES]; __shared__ float red[4]; __shared__ float hps[DD];
    float fi = g_f1[i]; float ev[4]; float m = -1e30f;
#pragma unroll
    for (int u = 0; u < 4; u++) {
        int j = d + u * 128;
        float x = fi + g_f2[j];
        x = (x > 0.0f) ? x : ALPHA * x;
        if (j == i) x = -1e30f;
        ev[u] = x; m = fmaxf(m, x);
    }
#pragma unroll
    for (int off = 16; off > 0; off >>= 1) m = fmaxf(m, __shfl_xor_sync(0xffffffffu, m, off));
    if ((d & 31) == 0) red[d >> 5] = m;
    __syncthreads();
    m = fmaxf(fmaxf(red[0], red[1]), fmaxf(red[2], red[3]));
    __syncthreads();
    float s = 0.0f;
#pragma unroll
    for (int u = 0; u < 4; u++) {
        int j = d + u * 128;
        float p = (j == i) ? 0.0f : expf(ev[u] - m);
        att[j] = p; s += p;
    }
#pragma unroll
    for (int off = 16; off > 0; off >>= 1) s += __shfl_xor_sync(0xffffffffu, s, off);
    if ((d & 31) == 0) red[d >> 5] = s;
    __syncthreads();
    float denom = red[0]+red[1]+red[2]+red[3];
    __syncthreads();
    float acc = 0.0f;
#pragma unroll 8
    for (int j = 0; j < O_NODES; j++) acc = fmaf(att[j], g_Wh[j * DD + d], acc);
    float hp = fmaxf(acc / denom, 0.0f);
    hps[d] = hp;
    __syncthreads();
    float A = 0.0f, C = 0.0f;
#pragma unroll 8
    for (int k = 0; k < DD; k++) {
        float h = hps[k];
        A = fmaf(h, W1[k * DD + d], A);
        C = fmaf(h, W1[(256 + k) * DD + d], C);
    }
    g_Ab[i * DD + d] = A + b1[d];
    g_C[i * DD + d] = C;
}

// ---------------- k_prepW: weights -> B-fragment layout (hi/lo bf16) --------
// B frag m16n8k16: reg q&1==0 -> k_local=(l&3)*2, q&1==1 -> k_local+8;
// n_local = l>>2. q<2: hi bf16 part, q>=2: lo (residual) part.
__global__ void k_prepW(const float* __restrict__ W1, const float* __restrict__ W2) {
    int idx = blockIdx.x * 256 + threadIdx.x;
    if (idx < 16384) {
        int q = idx & 3, ln = (idx >> 2) & 31, nt = (idx >> 7) & 15, kt = idx >> 11;
        int k = kt * 16 + (ln & 3) * 2 + (q & 1) * 8;
        int n = nt * 8 + (ln >> 2);
        float v0 = W1[(128 + k) * DD + n];
        float v1 = W1[(128 + k + 1) * DD + n];
        if (q < 2) g_w1f[idx] = pack2(v0, v1);
        else { uint32_t hi, lo; split2(v0, v1, hi, lo); g_w1f[idx] = lo; }
    }
    int idx2 = idx - 16384;
    if (idx2 >= 0 && idx2 < 49152) {
        int q = idx2 & 3, ln = (idx2 >> 2) & 31;
        int r = idx2 >> 7; int gnt = r % 48; int kt2 = r / 48;
        int k = kt2 * 16 + (ln & 3) * 2 + (q & 1) * 8;
        int n = gnt * 8 + (ln >> 2);
        float v0 = W2[k * 384 + n];
        float v1 = W2[(k + 1) * 384 + n];
        if (q < 2) g_w2f[idx2] = pack2(v0, v1);
        else { uint32_t hi, lo; split2(v0, v1, hi, lo); g_w2f[idx2] = lo; }
    }
}

// ---------------- kE: fused edge MLP (HMMA) ----------------------------------
// SMEM: [0, 67584) AC staging (128x132 f32); reused as W2 ring (2 x 32768)
//       [69632, 135168) W1 frags (16384 u32)
//       [135168, 136192) sm_s[2][128] f32
#define SM_W1 69632
#define SM_SS 135168
#define SM_TOTAL 136192

__device__ __forceinline__ void issue_w2_chunk(uint32_t smem_base, int tid, int ch) {
    uint32_t dst = smem_base + (uint32_t)(ch & 1) * 32768u;
    for (int i = tid; i < 2048; i += 256) {
        int kt2 = i >> 8, nt = (i >> 5) & 7, ln = i & 31;
        const uint32_t* src = g_w2f + (size_t)(((kt2 * 48) + ch * 8 + nt) * 32 + ln) * 4;
        cp_async16(dst + (uint32_t)i * 16u, src);
    }
    asm volatile("cp.async.commit_group;" ::: "memory");
}

__global__ void __launch_bounds__(256, 1) kE(const float* __restrict__ pred,
                                             const float* __restrict__ b2,
                                             float* __restrict__ outp) {
    extern __shared__ char smem[];
    uint32_t smem_base = smem_u32(smem);
    float* AC = (float*)smem;                       // [128][132]
    uint32_t* W1s = (uint32_t*)(smem + SM_W1);
    float* sm_s = (float*)(smem + SM_SS);           // [2][128]
    int tid = threadIdx.x, lane = tid & 31, wid = tid >> 5;
    int t0 = blockIdx.x * 256;

    for (int i = tid; i < 16384; i += 256) W1s[i] = g_w1f[i];
    sm_s[tid] = 0.0f;
    if (tid < 128) sm_s[128 + tid] = 0.0f;   // sm_s covers 256 floats; init all

    float acc[2][16][4];

    // ---- AC staging + acc init (two 128-row phases) ----
    for (int ph = 0; ph < 2; ph++) {
        __syncthreads();
        for (int i = tid; i < 128 * 128; i += 256) {
            int r = i >> 7, c = i & 127;
            int t = t0 + ph * 128 + r;
            int s = t / 511; int rr = t - s * 511; int o = rr + (rr >= s ? 1 : 0);
            AC[r * 132 + c] = g_Ab[s * DD + c] + g_C[o * DD + c];
        }
        __syncthreads();
        if ((wid >> 2) == ph) {
            int lr = (wid & 3) * 32;
#pragma unroll
            for (int mt = 0; mt < 2; mt++) {
                int r0 = lr + mt * 16 + (lane >> 2);
#pragma unroll
                for (int nt = 0; nt < 16; nt++) {
                    int col = nt * 8 + (lane & 3) * 2;
                    float2 v0 = *(float2*)&AC[r0 * 132 + col];
                    float2 v1 = *(float2*)&AC[(r0 + 8) * 132 + col];
                    acc[mt][nt][0] = v0.x; acc[mt][nt][1] = v0.y;
                    acc[mt][nt][2] = v1.x; acc[mt][nt][3] = v1.y;
                }
            }
        }
    }
    __syncthreads();                // AC region free -> becomes W2 ring
    issue_w2_chunk(smem_base, tid, 0);

    // ---- GEMM1: acc += P @ W1b  (split bf16, 3 terms) ----
    int gr0 = t0 + wid * 32 + (lane >> 2);
#pragma unroll 2
    for (int kt = 0; kt < 8; kt++) {
        int k0 = kt * 16 + (lane & 3) * 2;
        uint32_t ah[2][4], al[2][4];
#pragma unroll
        for (int mt = 0; mt < 2; mt++) {
            const float* bp = pred + (size_t)(gr0 + mt * 16) * DD;
            float2 x0 = *(const float2*)(bp + k0);
            float2 x1 = *(const float2*)(bp + 8 * DD + k0);
            float2 x2 = *(const float2*)(bp + k0 + 8);
            float2 x3 = *(const float2*)(bp + 8 * DD + k0 + 8);
            split2(x0.x, x0.y, ah[mt][0], al[mt][0]);
            split2(x1.x, x1.y, ah[mt][1], al[mt][1]);
            split2(x2.x, x2.y, ah[mt][2], al[mt][2]);
            split2(x3.x, x3.y, ah[mt][3], al[mt][3]);
        }
#pragma unroll
        for (int nt = 0; nt < 16; nt++) {
            uint4 B = *(const uint4*)&W1s[((kt * 16 + nt) * 32 + lane) * 4];
            mma_bf16(acc[0][nt], ah[0], B.x, B.y);
            mma_bf16(acc[0][nt], al[0], B.x, B.y);
            mma_bf16(acc[0][nt], ah[0], B.z, B.w);
            mma_bf16(acc[1][nt], ah[1], B.x, B.y);
            mma_bf16(acc[1][nt], al[1], B.x, B.y);
            mma_bf16(acc[1][nt], ah[1], B.z, B.w);
        }
    }

    // ---- relu + register repack: GEMM1 C-frags -> GEMM2 A-frags (hi/lo) ----
    uint32_t hh[2][8][4], hl[2][8][4];
#pragma unroll
    for (int mt = 0; mt < 2; mt++)
#pragma unroll
        for (int kq = 0; kq < 8; kq++) {
            float a0 = fmaxf(acc[mt][2 * kq][0], 0.0f);
            float a1 = fmaxf(acc[mt][2 * kq][1], 0.0f);
            float a2 = fmaxf(acc[mt][2 * kq][2], 0.0f);
            float a3 = fmaxf(acc[mt][2 * kq][3], 0.0f);
            float c0 = fmaxf(acc[mt][2 * kq + 1][0], 0.0f);
            float c1 = fmaxf(acc[mt][2 * kq + 1][1], 0.0f);
            float c2 = fmaxf(acc[mt][2 * kq + 1][2], 0.0f);
            float c3 = fmaxf(acc[mt][2 * kq + 1][3], 0.0f);
            split2(a0, a1, hh[mt][kq][0], hl[mt][kq][0]);   // a0: row g,  k<8
            split2(a2, a3, hh[mt][kq][1], hl[mt][kq][1]);   // a1: row g+8, k<8
            split2(c0, c1, hh[mt][kq][2], hl[mt][kq][2]);   // a2: row g,  k>=8
            split2(c2, c3, hh[mt][kq][3], hl[mt][kq][3]);   // a3: row g+8, k>=8
        }

    // ---- per-row metadata ----
    int sFirst = t0 / 511;
    int bnd = (sFirst + 1) * 511;
    int sR[4], oR[4], selR[4];
#pragma unroll
    for (int j = 0; j < 4; j++) {
        int gr = gr0 + j * 8;
        int s = gr / 511; int rr = gr - s * 511;
        sR[j] = s; oR[j] = rr + (rr >= s ? 1 : 0); selR[j] = (gr >= bnd) ? 1 : 0;
    }

    // ---- GEMM2: 6 chunks of 64 output cols ----
    for (int ch = 0; ch < 6; ch++) {
        if (ch < 5) {
            issue_w2_chunk(smem_base, tid, ch + 1);
            asm volatile("cp.async.wait_group 1;" ::: "memory");
        } else {
            asm volatile("cp.async.wait_group 0;" ::: "memory");
        }
        __syncthreads();
        const uint32_t* Ws = (const uint32_t*)(smem + (ch & 1) * 32768);

        float acc2[2][8][4];
#pragma unroll
        for (int mt = 0; mt < 2; mt++)
#pragma unroll
            for (int nt = 0; nt < 8; nt++) {
                float2 bb = *(const float2*)(b2 + ch * 64 + nt * 8 + 2 * (lane & 3));
                acc2[mt][nt][0] = bb.x; acc2[mt][nt][1] = bb.y;
                acc2[mt][nt][2] = bb.x; acc2[mt][nt][3] = bb.y;
            }
#pragma unroll
        for (int kq = 0; kq < 8; kq++) {
#pragma unroll
            for (int nt = 0; nt < 8; nt++) {
                uint4 B = *(const uint4*)&Ws[((kq * 8 + nt) * 32 + lane) * 4];
                mma_bf16(acc2[0][nt], hh[0][kq], B.x, B.y);
                mma_bf16(acc2[0][nt], hl[0][kq], B.x, B.y);
                mma_bf16(acc2[0][nt], hh[0][kq], B.z, B.w);
                mma_bf16(acc2[1][nt], hh[1][kq], B.x, B.y);
                mma_bf16(acc2[1][nt], hl[1][kq], B.x, B.y);
                mma_bf16(acc2[1][nt], hh[1][kq], B.z, B.w);
            }
        }

        // ---- epilogue for this 64-col chunk ----
#pragma unroll
        for (int mt = 0; mt < 2; mt++)
#pragma unroll
            for (int nt = 0; nt < 8; nt++) {
                int col = ch * 64 + nt * 8 + 2 * (lane & 3);
                float v0 = fmaxf(acc2[mt][nt][0], 0.0f);
                float v1 = fmaxf(acc2[mt][nt][1], 0.0f);
                float v2 = fmaxf(acc2[mt][nt][2], 0.0f);
                float v3 = fmaxf(acc2[mt][nt][3], 0.0f);
                int jA = mt * 2, jB = mt * 2 + 1;
                int grA = gr0 + jA * 8, grB = gr0 + jB * 8;
                if (ch < 2) {                               // new_s: SMEM reduce
                    atomicAdd(&sm_s[selR[jA] * 128 + col], v0);
                    atomicAdd(&sm_s[selR[jA] * 128 + col + 1], v1);
                    atomicAdd(&sm_s[selR[jB] * 128 + col], v2);
                    atomicAdd(&sm_s[selR[jB] * 128 + col + 1], v3);
                } else if (ch < 4) {                        // new_p: fp32 out
                    int cc = col - 128;
                    *(float2*)(outp + (size_t)grA * DD + cc) = make_float2(v0, v1);
                    *(float2*)(outp + (size_t)grB * DD + cc) = make_float2(v2, v3);
                } else {                                    // new_o: o-major bf16
                    int cc = col - 256;
                    *(uint32_t*)((__nv_bfloat16*)g_so + ((size_t)oR[jA] * 512 + sR[jA]) * DD + cc) = pack2(v0, v1);
                    *(uint32_t*)((__nv_bfloat16*)g_so + ((size_t)oR[jB] * 512 + sR[jB]) * DD + cc) = pack2(v2, v3);
                }
            }
        __syncthreads();
    }

    // ---- flush per-CTA new_s sums (<=2 segments per CTA) ----
    if (tid < 128) {
        atomicAdd(&g_pooled[sFirst * DD + tid], sm_s[tid]);
    } else if (bnd < t0 + 256) {
        int c = tid - 128;
        atomicAdd(&g_pooled[(sFirst + 1) * DD + c], sm_s[128 + c]);
    }
}

// ---------------- k_pool: add o-sums, divide by counts (=1022) --------------
__global__ void k_pool() {
    int i = blockIdx.x, c = threadIdx.x;
    float acc = g_pooled[i * DD + c];
    const __nv_bfloat16* p = g_so + (size_t)i * 512 * DD + c;
#pragma unroll 4
    for (int s = 0; s < 512; s++) {
        if (s == i) continue;
        acc += __bfloat162float(p[(size_t)s * DD]);
    }
    g_pooled[i * DD + c] = acc * (1.0f / 1022.0f);
}

// ---------------- K4: pooled -> MLP2 -> new_obj -----------------------------
__global__ void k4_out(const float* __restrict__ W3, const float* __restrict__ b3,
                       const float* __restrict__ W4, const float* __restrict__ b4,
                       float* __restrict__ out) {
    int i = blockIdx.x, j = threadIdx.x;  // 0..255
    __shared__ float pn[DD]; __shared__ float g1[256];
    if (j < DD) pn[j] = g_pooled[i * DD + j];
    __syncthreads();
    float acc = b3[j];
#pragma unroll 8
    for (int k = 0; k < DD; k++) acc = fmaf(pn[k], W3[k * 256 + j], acc);
    g1[j] = fmaxf(acc, 0.0f);
    __syncthreads();
    if (j < DD) {
        float acc2 = b4[j];
#pragma unroll 8
        for (int k = 0; k < 256; k++) acc2 = fmaf(g1[k], W4[k * DD + j], acc2);
        out[i * DD + j] = fmaxf(acc2, 0.0f);
    }
}

// ---------------- launch -----------------------------------------------------
extern "C" void kernel_launch(void* const* d_in, const int* in_sizes, int n_in,
                              void* d_out, int out_size) {
    const float* obj  = (const float*)d_in[0];
    const float* pred = (const float*)d_in[1];
    const float* W    = (const float*)d_in[3];
    const float* a    = (const float*)d_in[4];
    const float* W1   = (const float*)d_in[5];
    const float* b1   = (const float*)d_in[6];
    const float* W2   = (const float*)d_in[7];
    const float* b2   = (const float*)d_in[8];
    const float* W3   = (const float*)d_in[9];
    const float* b3   = (const float*)d_in[10];
    const float* W4   = (const float*)d_in[11];
    const float* b4   = (const float*)d_in[12];
    float* out = (float*)d_out;

    cudaFuncSetAttribute(kE, cudaFuncAttributeMaxDynamicSharedMemorySize, SM_TOTAL);

    k_init<<<256, 256>>>();
    k0_wh<<<O_NODES, 128>>>(obj, W, a);
    k2_attn<<<O_NODES, 128>>>(W1, b1);
    k_prepW<<<256, 256>>>(W1, W2);
    kE<<<N_CTAS, 256, SM_TOTAL>>>(pred, b2, out + O_NODES * DD);
    k_pool<<<O_NODES, 128>>>();
    k4_out<<<O_NODES, 256>>>(W3, b3, W4, b4, out);
}